// round 13
// baseline (speedup 1.0000x reference)
#include <cuda_runtime.h>
#include <cuda_fp16.h>
#include <cstdint>

// Problem constants
constexpr int B   = 32;
constexpr int DIM = 1024;
constexpr int MM  = 512;
constexpr int OUT_PER_B = DIM * (DIM + 1) / 2;    // 524800
constexpr float ALPHA = 0.4f;
constexpr float EPS   = 1e-5f;

// Scratch
__device__ float  g_dcov[(size_t)B * DIM * DIM];  // upper tiles only
__device__ __half g_xh[(size_t)B * DIM * MM];     // fp16 copy of features
__device__ float  g_part[B * 8 * 8 * 128];
__device__ float  g_mean[B * DIM];
__device__ float  g_tot[B];

// ---------------------------------------------------------------------------
__device__ __forceinline__ void mma_f16(float* c, const uint32_t* a, const uint32_t* b) {
    asm volatile(
        "mma.sync.aligned.m16n8k16.row.col.f32.f16.f16.f32 "
        "{%0,%1,%2,%3}, {%4,%5,%6,%7}, {%8,%9}, {%0,%1,%2,%3};"
        : "+f"(c[0]), "+f"(c[1]), "+f"(c[2]), "+f"(c[3])
        : "r"(a[0]), "r"(a[1]), "r"(a[2]), "r"(a[3]), "r"(b[0]), "r"(b[1]));
}
__device__ __forceinline__ void ldsm_x4(uint32_t& r0, uint32_t& r1, uint32_t& r2,
                                        uint32_t& r3, uint32_t addr) {
    asm volatile("ldmatrix.sync.aligned.m8n8.x4.shared.b16 {%0,%1,%2,%3}, [%4];"
        : "=r"(r0), "=r"(r1), "=r"(r2), "=r"(r3) : "r"(addr));
}
__device__ __forceinline__ uint32_t smem_u32(const void* p) {
    uint32_t a;
    asm("{ .reg .u64 t; cvta.to.shared.u64 t, %1; cvt.u32.u64 %0, t; }" : "=r"(a) : "l"(p));
    return a;
}
__device__ __forceinline__ void cp16(uint32_t saddr, const void* g) {
    asm volatile("cp.async.cg.shared.global [%0], [%1], 16;" :: "r"(saddr), "l"(g));
}
#define CP_COMMIT() asm volatile("cp.async.commit_group;" ::: "memory")
#define CP_WAIT1()  asm volatile("cp.async.wait_group 1;" ::: "memory")

// ---------------------------------------------------------------------------
// K0: fp32 -> fp16 conversion (8 elements per thread)
// ---------------------------------------------------------------------------
__global__ void tohalf_kernel(const float* __restrict__ x) {
    int idx = blockIdx.x * 256 + threadIdx.x;
    const float4* src = reinterpret_cast<const float4*>(x) + (size_t)idx * 2;
    float4 v0 = src[0], v1 = src[1];
    __align__(16) __half2 h[4];
    h[0] = __floats2half2_rn(v0.x, v0.y);
    h[1] = __floats2half2_rn(v0.z, v0.w);
    h[2] = __floats2half2_rn(v1.x, v1.y);
    h[3] = __floats2half2_rn(v1.z, v1.w);
    *reinterpret_cast<uint4*>(g_xh + (size_t)idx * 8) = *reinterpret_cast<uint4*>(h);
}

// ---------------------------------------------------------------------------
// K1: FP16 mma.sync SYRK 128x128 tile, cp.async 3-stage pipeline, ldmatrix
//     frags, fused row-norms + dcov epilogue + deterministic partial sums.
// ---------------------------------------------------------------------------
constexpr int NTILE  = DIM / 128;
constexpr int NPAIRS = NTILE * (NTILE + 1) / 2;   // 36
constexpr int BKH    = 64;                        // halfs per iter
constexpr int NITER  = MM / BKH;                  // 8
constexpr int STAGES = 3;
constexpr int ROWPH  = BKH + 8;                   // 72 halfs = 144 B row stride
constexpr int STAGE_HALFS = 128 * ROWPH;          // 9216
constexpr int STAGE_BYTES = STAGE_HALFS * 2;      // 18432
constexpr int SMEM_BYTES  = STAGES * 2 * STAGE_BYTES;  // 110592

constexpr int GQ_STEP   = 32 * MM;
constexpr int SQ_STEP   = 32 * ROWPH * 2;
constexpr int FRAG_STEP = 16 * ROWPH * 2;

__global__ __launch_bounds__(256, 2)
void syrk_dcov_mma(const float* __restrict__ x_unused) {
    extern __shared__ __align__(16) char smemc[];
    float* smem = reinterpret_cast<float*>(smemc);
    uint32_t sbase = smem_u32(smemc);

    int tid  = threadIdx.x;
    int wid  = tid >> 5;
    int lane = tid & 31;
    int grp  = lane >> 2;
    int qid  = lane & 3;
    int wm   = wid & 3;
    int wn   = wid >> 2;

    int p = blockIdx.x, bi = 0;
    while (p >= NTILE - bi) { p -= NTILE - bi; bi++; }
    int bj = bi + p;
    int b = blockIdx.y;

    const __half* baseA = g_xh + ((size_t)b * DIM + bi * 128) * MM
                               + (size_t)(tid >> 3) * MM + (tid & 7) * 8;
    const __half* baseB = g_xh + ((size_t)b * DIM + bj * 128) * MM
                               + (size_t)(tid >> 3) * MM + (tid & 7) * 8;
    uint32_t soff0 = (uint32_t)((tid >> 3) * ROWPH * 2 + (tid & 7) * 16);

    auto issue = [&](int s) {
        uint32_t ab = sbase + (uint32_t)(s % STAGES) * (2 * STAGE_BYTES) + soff0;
        uint32_t bb = ab + STAGE_BYTES;
        const __half* ga = baseA + s * BKH;
        const __half* gb = baseB + s * BKH;
        #pragma unroll
        for (int q = 0; q < 4; q++) {
            cp16(ab + q * SQ_STEP, ga + q * GQ_STEP);
            cp16(bb + q * SQ_STEP, gb + q * GQ_STEP);
        }
    };

    uint32_t aoff0 = (uint32_t)((wm * 32 + (lane & 15)) * (ROWPH * 2) + (lane >> 4) * 16);
    uint32_t boff0 = (uint32_t)((wn * 64 + ((lane >> 4) & 1) * 8 + (lane & 7)) * (ROWPH * 2)
                                + ((lane >> 3) & 1) * 16);

    uint32_t normoff = (uint32_t)((tid < 128 ? 0 : STAGE_HALFS) + (tid & 127) * ROWPH);
    float norm = 0.f;

    float c[2][8][4] = {};

    issue(0); CP_COMMIT();
    issue(1); CP_COMMIT();

    for (int it = 0; it < NITER; it++) {
        CP_WAIT1();
        __syncthreads();

        if (it + 2 < NITER) issue(it + 2);
        CP_COMMIT();

        uint32_t sbA = sbase + (uint32_t)(it % STAGES) * (2 * STAGE_BYTES);
        uint32_t sbB = sbA + STAGE_BYTES;

        {
            const uint4* nrow = reinterpret_cast<const uint4*>(
                reinterpret_cast<const __half*>(smemc)
                + (size_t)(it % STAGES) * (2 * STAGE_HALFS) + normoff);
            #pragma unroll
            for (int q8 = 0; q8 < 8; q8++) {
                uint4 u = nrow[q8];
                const __half2* hp = reinterpret_cast<const __half2*>(&u);
                #pragma unroll
                for (int e = 0; e < 4; e++) {
                    float2 f = __half22float2(hp[e]);
                    norm += f.x * f.x + f.y * f.y;
                }
            }
        }

        uint32_t aA = sbA + aoff0;
        uint32_t aB = sbB + boff0;

        #pragma unroll
        for (int ks = 0; ks < 4; ks++) {
            uint32_t kb = ks * 32;
            uint32_t af[2][4];
            #pragma unroll
            for (int mt = 0; mt < 2; mt++)
                ldsm_x4(af[mt][0], af[mt][1], af[mt][2], af[mt][3],
                        aA + mt * FRAG_STEP + kb);
            uint32_t bf[8][2];
            #pragma unroll
            for (int pr = 0; pr < 4; pr++)
                ldsm_x4(bf[2*pr][0], bf[2*pr][1], bf[2*pr+1][0], bf[2*pr+1][1],
                        aB + pr * FRAG_STEP + kb);
            #pragma unroll
            for (int mt = 0; mt < 2; mt++)
                #pragma unroll
                for (int nt = 0; nt < 8; nt++)
                    mma_f16(c[mt][nt], af[mt], bf[nt]);
        }
    }

    __syncthreads();
    float* dn = smem + 768;
    dn[tid] = norm * (1.f / (2.f * MM));
    __syncthreads();

    // ---------------- Epilogue ----------------
    int i0 = bi * 128, j0 = bj * 128;
    const float invM = 1.f / (float)MM;
    float* dcb = g_dcov + (size_t)b * DIM * DIM;
    bool offdiag = (bi != bj);

    float dj[8][2];
    #pragma unroll
    for (int nt = 0; nt < 8; nt++) {
        int jl = wn * 64 + nt * 8 + 2 * qid;
        dj[nt][0] = dn[128 + jl];
        dj[nt][1] = dn[128 + jl + 1];
    }

    float rsum[2][2] = {};
    float csum[8][2] = {};

    #pragma unroll
    for (int mt = 0; mt < 2; mt++) {
        #pragma unroll
        for (int rr = 0; rr < 2; rr++) {
            int il = wm * 32 + mt * 16 + grp + rr * 8;
            int i = i0 + il;
            float di = dn[il];
            #pragma unroll
            for (int nt = 0; nt < 8; nt++) {
                int j = j0 + wn * 64 + nt * 8 + 2 * qid;
                float dot0 = c[mt][nt][rr * 2 + 0];
                float dot1 = c[mt][nt][rr * 2 + 1];
                float d0 = (i == j)     ? 0.f : fmaxf(di + dj[nt][0] - dot0 * invM, 0.f);
                float d1 = (i == j + 1) ? 0.f : fmaxf(di + dj[nt][1] - dot1 * invM, 0.f);
                float v0 = exp2f(ALPHA * log2f(d0 + EPS));
                float v1 = exp2f(ALPHA * log2f(d1 + EPS));
                *reinterpret_cast<float2*>(dcb + (size_t)i * DIM + j) = make_float2(v0, v1);
                rsum[mt][rr] += v0 + v1;
                csum[nt][0]  += v0;
                csum[nt][1]  += v1;
            }
        }
    }

    #pragma unroll
    for (int mt = 0; mt < 2; mt++)
        #pragma unroll
        for (int rr = 0; rr < 2; rr++) {
            rsum[mt][rr] += __shfl_xor_sync(0xFFFFFFFFu, rsum[mt][rr], 1);
            rsum[mt][rr] += __shfl_xor_sync(0xFFFFFFFFu, rsum[mt][rr], 2);
        }
    #pragma unroll
    for (int nt = 0; nt < 8; nt++)
        #pragma unroll
        for (int h = 0; h < 2; h++) {
            csum[nt][h] += __shfl_xor_sync(0xFFFFFFFFu, csum[nt][h], 4);
            csum[nt][h] += __shfl_xor_sync(0xFFFFFFFFu, csum[nt][h], 8);
            csum[nt][h] += __shfl_xor_sync(0xFFFFFFFFu, csum[nt][h], 16);
        }

    __syncthreads();
    float* rbuf = smem;
    float* cbuf = smem + 256;
    if (qid == 0) {
        #pragma unroll
        for (int mt = 0; mt < 2; mt++)
            #pragma unroll
            for (int rr = 0; rr < 2; rr++)
                rbuf[wn * 128 + wm * 32 + mt * 16 + rr * 8 + grp] = rsum[mt][rr];
    }
    if (grp == 0) {
        #pragma unroll
        for (int nt = 0; nt < 8; nt++) {
            cbuf[wm * 128 + wn * 64 + nt * 8 + 2 * qid + 0] = csum[nt][0];
            cbuf[wm * 128 + wn * 64 + nt * 8 + 2 * qid + 1] = csum[nt][1];
        }
    }
    __syncthreads();

    if (tid < 128) {
        float rs = rbuf[tid] + rbuf[128 + tid];
        g_part[(((size_t)b * 8 + bi) * 8 + bj) * 128 + tid] = rs;
    } else if (offdiag) {
        int t = tid - 128;
        float cs = cbuf[t] + cbuf[128 + t] + cbuf[256 + t] + cbuf[384 + t];
        g_part[(((size_t)b * 8 + bj) * 8 + bi) * 128 + t] = cs;
    }
}

// ---------------------------------------------------------------------------
// K2: row means + total mean. grid=B, block=1024.
// ---------------------------------------------------------------------------
__global__ void means_kernel() {
    int b = blockIdx.x;
    int i = threadIdx.x;
    int ti = i >> 7;
    int ii = i & 127;
    float s = 0.f;
    #pragma unroll
    for (int tj = 0; tj < 8; tj++)
        s += g_part[(((size_t)b * 8 + ti) * 8 + tj) * 128 + ii];
    float m = s * (1.f / DIM);
    g_mean[b * DIM + i] = m;

    __shared__ float sh[32];
    float t = m;
    #pragma unroll
    for (int off = 16; off > 0; off >>= 1)
        t += __shfl_down_sync(0xFFFFFFFFu, t, off);
    if ((i & 31) == 0) sh[i >> 5] = t;
    __syncthreads();
    if (i < 32) {
        float u = sh[i];
        #pragma unroll
        for (int off = 16; off > 0; off >>= 1)
            u += __shfl_down_sync(0xFFFFFFFFu, u, off);
        if (i == 0) g_tot[b] = u * (1.f / DIM);
    }
}

// ---------------------------------------------------------------------------
// K3: warp-per-row triu, 4-way MLP-batched, streaming cache hints.
// dcov rows read once -> __ldcs; out never re-read -> __stcs.
// ---------------------------------------------------------------------------
__device__ __forceinline__ long long triu_off(int i) {
    return (long long)i * (2 * DIM + 1 - i) / 2;
}

__global__ void triu_rows_kernel(float* __restrict__ out) {
    int b = blockIdx.y;
    int i = blockIdx.x * 8 + (threadIdx.x >> 5);
    int lane = threadIdx.x & 31;
    const float* row  = g_dcov + ((size_t)b * DIM + i) * DIM;
    const float* mean = g_mean + b * DIM;
    float adj = g_tot[b] - mean[i];
    long long base = (long long)b * OUT_PER_B + triu_off(i) - i;

    int j = i + lane;
    // 4-way batched: 8 independent loads in flight before first store
    for (; j + 96 < DIM; j += 128) {
        float r0 = __ldcs(row + j);
        float r1 = __ldcs(row + j + 32);
        float r2 = __ldcs(row + j + 64);
        float r3 = __ldcs(row + j + 96);
        float m0 = mean[j];
        float m1 = mean[j + 32];
        float m2 = mean[j + 64];
        float m3 = mean[j + 96];
        __stcs(out + base + j,      r0 - m0 + adj);
        __stcs(out + base + j + 32, r1 - m1 + adj);
        __stcs(out + base + j + 64, r2 - m2 + adj);
        __stcs(out + base + j + 96, r3 - m3 + adj);
    }
    for (; j < DIM; j += 32)
        __stcs(out + base + j, __ldcs(row + j) - mean[j] + adj);
}

// ---------------------------------------------------------------------------
extern "C" void kernel_launch(void* const* d_in, const int* in_sizes, int n_in,
                              void* d_out, int out_size) {
    const float* x = (const float*)d_in[0];
    float* out = (float*)d_out;

    static bool attr_set = false;
    if (!attr_set) {
        cudaFuncSetAttribute(syrk_dcov_mma,
                             cudaFuncAttributeMaxDynamicSharedMemorySize, SMEM_BYTES);
        attr_set = true;
    }

    tohalf_kernel<<<(B * DIM * MM) / (256 * 8), 256>>>(x);
    syrk_dcov_mma<<<dim3(NPAIRS, B), 256, SMEM_BYTES>>>(x);
    means_kernel<<<B, 1024>>>();
    triu_rows_kernel<<<dim3(DIM / 8, B), 256>>>(out);
}

// round 14
// speedup vs baseline: 1.0630x; 1.0630x over previous
#include <cuda_runtime.h>
#include <cuda_fp16.h>
#include <cstdint>

// Problem constants
constexpr int B   = 32;
constexpr int DIM = 1024;
constexpr int MM  = 512;
constexpr int OUT_PER_B = DIM * (DIM + 1) / 2;    // 524800
constexpr float ALPHA = 0.4f;
constexpr float EPS   = 1e-5f;

// Scratch
__device__ __half g_dcov[(size_t)B * DIM * DIM];  // (v - 1) as fp16, upper tiles
__device__ __half g_xh[(size_t)B * DIM * MM];     // fp16 copy of features
__device__ float  g_part[B * 8 * 8 * 128];
__device__ float  g_mean[B * DIM];
__device__ float  g_tot[B];

// ---------------------------------------------------------------------------
__device__ __forceinline__ void mma_f16(float* c, const uint32_t* a, const uint32_t* b) {
    asm volatile(
        "mma.sync.aligned.m16n8k16.row.col.f32.f16.f16.f32 "
        "{%0,%1,%2,%3}, {%4,%5,%6,%7}, {%8,%9}, {%0,%1,%2,%3};"
        : "+f"(c[0]), "+f"(c[1]), "+f"(c[2]), "+f"(c[3])
        : "r"(a[0]), "r"(a[1]), "r"(a[2]), "r"(a[3]), "r"(b[0]), "r"(b[1]));
}
__device__ __forceinline__ void ldsm_x4(uint32_t& r0, uint32_t& r1, uint32_t& r2,
                                        uint32_t& r3, uint32_t addr) {
    asm volatile("ldmatrix.sync.aligned.m8n8.x4.shared.b16 {%0,%1,%2,%3}, [%4];"
        : "=r"(r0), "=r"(r1), "=r"(r2), "=r"(r3) : "r"(addr));
}
__device__ __forceinline__ uint32_t smem_u32(const void* p) {
    uint32_t a;
    asm("{ .reg .u64 t; cvta.to.shared.u64 t, %1; cvt.u32.u64 %0, t; }" : "=r"(a) : "l"(p));
    return a;
}
__device__ __forceinline__ void cp16(uint32_t saddr, const void* g) {
    asm volatile("cp.async.cg.shared.global [%0], [%1], 16;" :: "r"(saddr), "l"(g));
}
#define CP_COMMIT() asm volatile("cp.async.commit_group;" ::: "memory")
#define CP_WAIT1()  asm volatile("cp.async.wait_group 1;" ::: "memory")

// ---------------------------------------------------------------------------
// K0: fp32 -> fp16 conversion (8 elements per thread)
// ---------------------------------------------------------------------------
__global__ void tohalf_kernel(const float* __restrict__ x) {
    int idx = blockIdx.x * 256 + threadIdx.x;
    const float4* src = reinterpret_cast<const float4*>(x) + (size_t)idx * 2;
    float4 v0 = src[0], v1 = src[1];
    __align__(16) __half2 h[4];
    h[0] = __floats2half2_rn(v0.x, v0.y);
    h[1] = __floats2half2_rn(v0.z, v0.w);
    h[2] = __floats2half2_rn(v1.x, v1.y);
    h[3] = __floats2half2_rn(v1.z, v1.w);
    *reinterpret_cast<uint4*>(g_xh + (size_t)idx * 8) = *reinterpret_cast<uint4*>(h);
}

// ---------------------------------------------------------------------------
// K1: FP16 mma.sync SYRK 128x128 tile, cp.async 3-stage pipeline, ldmatrix
//     frags, fused row-norms + dcov epilogue + deterministic partial sums.
//     dcov stored as fp16 offset (v - 1).
// ---------------------------------------------------------------------------
constexpr int NTILE  = DIM / 128;
constexpr int NPAIRS = NTILE * (NTILE + 1) / 2;   // 36
constexpr int BKH    = 64;                        // halfs per iter
constexpr int NITER  = MM / BKH;                  // 8
constexpr int STAGES = 3;
constexpr int ROWPH  = BKH + 8;                   // 72 halfs = 144 B row stride
constexpr int STAGE_HALFS = 128 * ROWPH;          // 9216
constexpr int STAGE_BYTES = STAGE_HALFS * 2;      // 18432
constexpr int SMEM_BYTES  = STAGES * 2 * STAGE_BYTES;  // 110592

constexpr int GQ_STEP   = 32 * MM;
constexpr int SQ_STEP   = 32 * ROWPH * 2;
constexpr int FRAG_STEP = 16 * ROWPH * 2;

__global__ __launch_bounds__(256, 2)
void syrk_dcov_mma(const float* __restrict__ x_unused) {
    extern __shared__ __align__(16) char smemc[];
    float* smem = reinterpret_cast<float*>(smemc);
    uint32_t sbase = smem_u32(smemc);

    int tid  = threadIdx.x;
    int wid  = tid >> 5;
    int lane = tid & 31;
    int grp  = lane >> 2;
    int qid  = lane & 3;
    int wm   = wid & 3;
    int wn   = wid >> 2;

    int p = blockIdx.x, bi = 0;
    while (p >= NTILE - bi) { p -= NTILE - bi; bi++; }
    int bj = bi + p;
    int b = blockIdx.y;

    const __half* baseA = g_xh + ((size_t)b * DIM + bi * 128) * MM
                               + (size_t)(tid >> 3) * MM + (tid & 7) * 8;
    const __half* baseB = g_xh + ((size_t)b * DIM + bj * 128) * MM
                               + (size_t)(tid >> 3) * MM + (tid & 7) * 8;
    uint32_t soff0 = (uint32_t)((tid >> 3) * ROWPH * 2 + (tid & 7) * 16);

    auto issue = [&](int s) {
        uint32_t ab = sbase + (uint32_t)(s % STAGES) * (2 * STAGE_BYTES) + soff0;
        uint32_t bb = ab + STAGE_BYTES;
        const __half* ga = baseA + s * BKH;
        const __half* gb = baseB + s * BKH;
        #pragma unroll
        for (int q = 0; q < 4; q++) {
            cp16(ab + q * SQ_STEP, ga + q * GQ_STEP);
            cp16(bb + q * SQ_STEP, gb + q * GQ_STEP);
        }
    };

    uint32_t aoff0 = (uint32_t)((wm * 32 + (lane & 15)) * (ROWPH * 2) + (lane >> 4) * 16);
    uint32_t boff0 = (uint32_t)((wn * 64 + ((lane >> 4) & 1) * 8 + (lane & 7)) * (ROWPH * 2)
                                + ((lane >> 3) & 1) * 16);

    uint32_t normoff = (uint32_t)((tid < 128 ? 0 : STAGE_HALFS) + (tid & 127) * ROWPH);
    float norm = 0.f;

    float c[2][8][4] = {};

    issue(0); CP_COMMIT();
    issue(1); CP_COMMIT();

    for (int it = 0; it < NITER; it++) {
        CP_WAIT1();
        __syncthreads();

        if (it + 2 < NITER) issue(it + 2);
        CP_COMMIT();

        uint32_t sbA = sbase + (uint32_t)(it % STAGES) * (2 * STAGE_BYTES);
        uint32_t sbB = sbA + STAGE_BYTES;

        {
            const uint4* nrow = reinterpret_cast<const uint4*>(
                reinterpret_cast<const __half*>(smemc)
                + (size_t)(it % STAGES) * (2 * STAGE_HALFS) + normoff);
            #pragma unroll
            for (int q8 = 0; q8 < 8; q8++) {
                uint4 u = nrow[q8];
                const __half2* hp = reinterpret_cast<const __half2*>(&u);
                #pragma unroll
                for (int e = 0; e < 4; e++) {
                    float2 f = __half22float2(hp[e]);
                    norm += f.x * f.x + f.y * f.y;
                }
            }
        }

        uint32_t aA = sbA + aoff0;
        uint32_t aB = sbB + boff0;

        #pragma unroll
        for (int ks = 0; ks < 4; ks++) {
            uint32_t kb = ks * 32;
            uint32_t af[2][4];
            #pragma unroll
            for (int mt = 0; mt < 2; mt++)
                ldsm_x4(af[mt][0], af[mt][1], af[mt][2], af[mt][3],
                        aA + mt * FRAG_STEP + kb);
            uint32_t bf[8][2];
            #pragma unroll
            for (int pr = 0; pr < 4; pr++)
                ldsm_x4(bf[2*pr][0], bf[2*pr][1], bf[2*pr+1][0], bf[2*pr+1][1],
                        aB + pr * FRAG_STEP + kb);
            #pragma unroll
            for (int mt = 0; mt < 2; mt++)
                #pragma unroll
                for (int nt = 0; nt < 8; nt++)
                    mma_f16(c[mt][nt], af[mt], bf[nt]);
        }
    }

    __syncthreads();
    float* dn = smem + 768;
    dn[tid] = norm * (1.f / (2.f * MM));
    __syncthreads();

    // ---------------- Epilogue ----------------
    int i0 = bi * 128, j0 = bj * 128;
    const float invM = 1.f / (float)MM;
    __half* dcb = g_dcov + (size_t)b * DIM * DIM;
    bool offdiag = (bi != bj);

    float dj[8][2];
    #pragma unroll
    for (int nt = 0; nt < 8; nt++) {
        int jl = wn * 64 + nt * 8 + 2 * qid;
        dj[nt][0] = dn[128 + jl];
        dj[nt][1] = dn[128 + jl + 1];
    }

    float rsum[2][2] = {};
    float csum[8][2] = {};

    #pragma unroll
    for (int mt = 0; mt < 2; mt++) {
        #pragma unroll
        for (int rr = 0; rr < 2; rr++) {
            int il = wm * 32 + mt * 16 + grp + rr * 8;
            int i = i0 + il;
            float di = dn[il];
            #pragma unroll
            for (int nt = 0; nt < 8; nt++) {
                int j = j0 + wn * 64 + nt * 8 + 2 * qid;
                float dot0 = c[mt][nt][rr * 2 + 0];
                float dot1 = c[mt][nt][rr * 2 + 1];
                float d0 = (i == j)     ? 0.f : fmaxf(di + dj[nt][0] - dot0 * invM, 0.f);
                float d1 = (i == j + 1) ? 0.f : fmaxf(di + dj[nt][1] - dot1 * invM, 0.f);
                float v0 = exp2f(ALPHA * log2f(d0 + EPS));
                float v1 = exp2f(ALPHA * log2f(d1 + EPS));
                // store (v - 1) in fp16: small magnitudes -> tight ulp
                *reinterpret_cast<__half2*>(dcb + (size_t)i * DIM + j) =
                    __floats2half2_rn(v0 - 1.0f, v1 - 1.0f);
                rsum[mt][rr] += v0 + v1;
                csum[nt][0]  += v0;
                csum[nt][1]  += v1;
            }
        }
    }

    #pragma unroll
    for (int mt = 0; mt < 2; mt++)
        #pragma unroll
        for (int rr = 0; rr < 2; rr++) {
            rsum[mt][rr] += __shfl_xor_sync(0xFFFFFFFFu, rsum[mt][rr], 1);
            rsum[mt][rr] += __shfl_xor_sync(0xFFFFFFFFu, rsum[mt][rr], 2);
        }
    #pragma unroll
    for (int nt = 0; nt < 8; nt++)
        #pragma unroll
        for (int h = 0; h < 2; h++) {
            csum[nt][h] += __shfl_xor_sync(0xFFFFFFFFu, csum[nt][h], 4);
            csum[nt][h] += __shfl_xor_sync(0xFFFFFFFFu, csum[nt][h], 8);
            csum[nt][h] += __shfl_xor_sync(0xFFFFFFFFu, csum[nt][h], 16);
        }

    __syncthreads();
    float* rbuf = smem;
    float* cbuf = smem + 256;
    if (qid == 0) {
        #pragma unroll
        for (int mt = 0; mt < 2; mt++)
            #pragma unroll
            for (int rr = 0; rr < 2; rr++)
                rbuf[wn * 128 + wm * 32 + mt * 16 + rr * 8 + grp] = rsum[mt][rr];
    }
    if (grp == 0) {
        #pragma unroll
        for (int nt = 0; nt < 8; nt++) {
            cbuf[wm * 128 + wn * 64 + nt * 8 + 2 * qid + 0] = csum[nt][0];
            cbuf[wm * 128 + wn * 64 + nt * 8 + 2 * qid + 1] = csum[nt][1];
        }
    }
    __syncthreads();

    if (tid < 128) {
        float rs = rbuf[tid] + rbuf[128 + tid];
        g_part[(((size_t)b * 8 + bi) * 8 + bj) * 128 + tid] = rs;
    } else if (offdiag) {
        int t = tid - 128;
        float cs = cbuf[t] + cbuf[128 + t] + cbuf[256 + t] + cbuf[384 + t];
        g_part[(((size_t)b * 8 + bj) * 8 + bi) * 128 + t] = cs;
    }
}

// ---------------------------------------------------------------------------
// K2: row means + total mean. grid=B, block=1024.  (means are of v, fp32)
// ---------------------------------------------------------------------------
__global__ void means_kernel() {
    int b = blockIdx.x;
    int i = threadIdx.x;
    int ti = i >> 7;
    int ii = i & 127;
    float s = 0.f;
    #pragma unroll
    for (int tj = 0; tj < 8; tj++)
        s += g_part[(((size_t)b * 8 + ti) * 8 + tj) * 128 + ii];
    float m = s * (1.f / DIM);
    g_mean[b * DIM + i] = m;

    __shared__ float sh[32];
    float t = m;
    #pragma unroll
    for (int off = 16; off > 0; off >>= 1)
        t += __shfl_down_sync(0xFFFFFFFFu, t, off);
    if ((i & 31) == 0) sh[i >> 5] = t;
    __syncthreads();
    if (i < 32) {
        float u = sh[i];
        #pragma unroll
        for (int off = 16; off > 0; off >>= 1)
            u += __shfl_down_sync(0xFFFFFFFFu, u, off);
        if (i == 0) g_tot[b] = u * (1.f / DIM);
    }
}

// ---------------------------------------------------------------------------
// K3: warp-per-row triu (R11 shape), fp16 offset reads.
// out = v_off + 1 - mean[i] - mean[j] + tot  =  v_off - mean[j] + adj
// with adj = tot + 1 - mean[i].
// ---------------------------------------------------------------------------
__device__ __forceinline__ long long triu_off(int i) {
    return (long long)i * (2 * DIM + 1 - i) / 2;
}

__global__ void triu_rows_kernel(float* __restrict__ out) {
    int b = blockIdx.y;
    int i = blockIdx.x * 8 + (threadIdx.x >> 5);
    int lane = threadIdx.x & 31;
    const __half* row  = g_dcov + ((size_t)b * DIM + i) * DIM;
    const float* mean = g_mean + b * DIM;
    float adj = g_tot[b] + 1.0f - mean[i];
    long long base = (long long)b * OUT_PER_B + triu_off(i) - i;
    for (int j = i + lane; j < DIM; j += 32)
        out[base + j] = __half2float(row[j]) - mean[j] + adj;
}

// ---------------------------------------------------------------------------
extern "C" void kernel_launch(void* const* d_in, const int* in_sizes, int n_in,
                              void* d_out, int out_size) {
    const float* x = (const float*)d_in[0];
    float* out = (float*)d_out;

    static bool attr_set = false;
    if (!attr_set) {
        cudaFuncSetAttribute(syrk_dcov_mma,
                             cudaFuncAttributeMaxDynamicSharedMemorySize, SMEM_BYTES);
        attr_set = true;
    }

    tohalf_kernel<<<(B * DIM * MM) / (256 * 8), 256>>>(x);
    syrk_dcov_mma<<<dim3(NPAIRS, B), 256, SMEM_BYTES>>>(x);
    means_kernel<<<B, 1024>>>();
    triu_rows_kernel<<<dim3(DIM / 8, B), 256>>>(out);
}

// round 15
// speedup vs baseline: 1.1740x; 1.1045x over previous
#include <cuda_runtime.h>
#include <cuda_fp16.h>
#include <cstdint>

// Problem constants
constexpr int B   = 32;
constexpr int DIM = 1024;
constexpr int MM  = 512;
constexpr int OUT_PER_B = DIM * (DIM + 1) / 2;    // 524800
constexpr float ALPHA = 0.4f;
constexpr float EPS   = 1e-5f;

// Scratch
__device__ __half g_dcov[(size_t)B * DIM * DIM];  // (v - 1) as fp16, upper tiles
__device__ __half g_xh[(size_t)B * DIM * MM];     // fp16 copy of features
__device__ float  g_diag[B * DIM];
__device__ float  g_part[B * 8 * 8 * 128];
__device__ float  g_mean[B * DIM];
__device__ float  g_tot[B];

// ---------------------------------------------------------------------------
__device__ __forceinline__ void mma_f16(float* c, const uint32_t* a, const uint32_t* b) {
    asm volatile(
        "mma.sync.aligned.m16n8k16.row.col.f32.f16.f16.f32 "
        "{%0,%1,%2,%3}, {%4,%5,%6,%7}, {%8,%9}, {%0,%1,%2,%3};"
        : "+f"(c[0]), "+f"(c[1]), "+f"(c[2]), "+f"(c[3])
        : "r"(a[0]), "r"(a[1]), "r"(a[2]), "r"(a[3]), "r"(b[0]), "r"(b[1]));
}
__device__ __forceinline__ void ldsm_x4(uint32_t& r0, uint32_t& r1, uint32_t& r2,
                                        uint32_t& r3, uint32_t addr) {
    asm volatile("ldmatrix.sync.aligned.m8n8.x4.shared.b16 {%0,%1,%2,%3}, [%4];"
        : "=r"(r0), "=r"(r1), "=r"(r2), "=r"(r3) : "r"(addr));
}
__device__ __forceinline__ uint32_t smem_u32(const void* p) {
    uint32_t a;
    asm("{ .reg .u64 t; cvta.to.shared.u64 t, %1; cvt.u32.u64 %0, t; }" : "=r"(a) : "l"(p));
    return a;
}
__device__ __forceinline__ void cp16(uint32_t saddr, const void* g) {
    asm volatile("cp.async.cg.shared.global [%0], [%1], 16;" :: "r"(saddr), "l"(g));
}
#define CP_COMMIT() asm volatile("cp.async.commit_group;" ::: "memory")
#define CP_WAIT1()  asm volatile("cp.async.wait_group 1;" ::: "memory")

// ---------------------------------------------------------------------------
// K0: fused fp32->fp16 convert + row-norm (diag). One warp per row.
// ---------------------------------------------------------------------------
__global__ void tohalf_diag_kernel(const float* __restrict__ x) {
    int row  = blockIdx.x * 8 + (threadIdx.x >> 5);   // B*DIM rows
    int lane = threadIdx.x & 31;
    const float4* src = reinterpret_cast<const float4*>(x + (size_t)row * MM);
    uint2* dst = reinterpret_cast<uint2*>(g_xh + (size_t)row * MM);
    float s = 0.f;
    #pragma unroll
    for (int k = 0; k < 4; k++) {
        float4 v = src[lane + 32 * k];
        s += v.x * v.x + v.y * v.y + v.z * v.z + v.w * v.w;
        __half2 h0 = __floats2half2_rn(v.x, v.y);
        __half2 h1 = __floats2half2_rn(v.z, v.w);
        uint2 u;
        u.x = *reinterpret_cast<uint32_t*>(&h0);
        u.y = *reinterpret_cast<uint32_t*>(&h1);
        dst[lane + 32 * k] = u;
    }
    #pragma unroll
    for (int off = 16; off > 0; off >>= 1)
        s += __shfl_down_sync(0xFFFFFFFFu, s, off);
    if (lane == 0) g_diag[row] = s * (1.f / (2.f * MM));
}

// ---------------------------------------------------------------------------
// K1: FP16 mma.sync SYRK 128x128 tile, cp.async 3-stage pipeline, ldmatrix
//     frags, dcov epilogue (fp16 offset store) + deterministic partial sums.
//     Norm work removed from mainloop (lives in tohalf_diag).
// ---------------------------------------------------------------------------
constexpr int NTILE  = DIM / 128;
constexpr int NPAIRS = NTILE * (NTILE + 1) / 2;   // 36
constexpr int BKH    = 64;                        // halfs per iter
constexpr int NITER  = MM / BKH;                  // 8
constexpr int STAGES = 3;
constexpr int ROWPH  = BKH + 8;                   // 72 halfs = 144 B row stride
constexpr int STAGE_HALFS = 128 * ROWPH;          // 9216
constexpr int STAGE_BYTES = STAGE_HALFS * 2;      // 18432
constexpr int SMEM_BYTES  = STAGES * 2 * STAGE_BYTES;  // 110592

constexpr int GQ_STEP   = 32 * MM;
constexpr int SQ_STEP   = 32 * ROWPH * 2;
constexpr int FRAG_STEP = 16 * ROWPH * 2;

__global__ __launch_bounds__(256, 2)
void syrk_dcov_mma(const float* __restrict__ x_unused) {
    extern __shared__ __align__(16) char smemc[];
    float* smem = reinterpret_cast<float*>(smemc);
    uint32_t sbase = smem_u32(smemc);

    int tid  = threadIdx.x;
    int wid  = tid >> 5;
    int lane = tid & 31;
    int grp  = lane >> 2;
    int qid  = lane & 3;
    int wm   = wid & 3;
    int wn   = wid >> 2;

    int p = blockIdx.x, bi = 0;
    while (p >= NTILE - bi) { p -= NTILE - bi; bi++; }
    int bj = bi + p;
    int b = blockIdx.y;

    const __half* baseA = g_xh + ((size_t)b * DIM + bi * 128) * MM
                               + (size_t)(tid >> 3) * MM + (tid & 7) * 8;
    const __half* baseB = g_xh + ((size_t)b * DIM + bj * 128) * MM
                               + (size_t)(tid >> 3) * MM + (tid & 7) * 8;
    uint32_t soff0 = (uint32_t)((tid >> 3) * ROWPH * 2 + (tid & 7) * 16);

    auto issue = [&](int s) {
        uint32_t ab = sbase + (uint32_t)(s % STAGES) * (2 * STAGE_BYTES) + soff0;
        uint32_t bb = ab + STAGE_BYTES;
        const __half* ga = baseA + s * BKH;
        const __half* gb = baseB + s * BKH;
        #pragma unroll
        for (int q = 0; q < 4; q++) {
            cp16(ab + q * SQ_STEP, ga + q * GQ_STEP);
            cp16(bb + q * SQ_STEP, gb + q * GQ_STEP);
        }
    };

    uint32_t aoff0 = (uint32_t)((wm * 32 + (lane & 15)) * (ROWPH * 2) + (lane >> 4) * 16);
    uint32_t boff0 = (uint32_t)((wn * 64 + ((lane >> 4) & 1) * 8 + (lane & 7)) * (ROWPH * 2)
                                + ((lane >> 3) & 1) * 16);

    float c[2][8][4] = {};

    issue(0); CP_COMMIT();
    issue(1); CP_COMMIT();

    for (int it = 0; it < NITER; it++) {
        CP_WAIT1();
        __syncthreads();

        if (it + 2 < NITER) issue(it + 2);
        CP_COMMIT();

        uint32_t sbA = sbase + (uint32_t)(it % STAGES) * (2 * STAGE_BYTES);
        uint32_t sbB = sbA + STAGE_BYTES;

        uint32_t aA = sbA + aoff0;
        uint32_t aB = sbB + boff0;

        #pragma unroll
        for (int ks = 0; ks < 4; ks++) {
            uint32_t kb = ks * 32;
            uint32_t af[2][4];
            #pragma unroll
            for (int mt = 0; mt < 2; mt++)
                ldsm_x4(af[mt][0], af[mt][1], af[mt][2], af[mt][3],
                        aA + mt * FRAG_STEP + kb);
            uint32_t bf[8][2];
            #pragma unroll
            for (int pr = 0; pr < 4; pr++)
                ldsm_x4(bf[2*pr][0], bf[2*pr][1], bf[2*pr+1][0], bf[2*pr+1][1],
                        aB + pr * FRAG_STEP + kb);
            #pragma unroll
            for (int mt = 0; mt < 2; mt++)
                #pragma unroll
                for (int nt = 0; nt < 8; nt++)
                    mma_f16(c[mt][nt], af[mt], bf[nt]);
        }
    }

    // ---------------- Epilogue ----------------
    int i0 = bi * 128, j0 = bj * 128;
    const float invM = 1.f / (float)MM;
    __half* dcb = g_dcov + (size_t)b * DIM * DIM;
    bool offdiag = (bi != bj);
    const float* dgb = g_diag + b * DIM;

    float dj[8][2];
    #pragma unroll
    for (int nt = 0; nt < 8; nt++) {
        int j = j0 + wn * 64 + nt * 8 + 2 * qid;
        dj[nt][0] = dgb[j];
        dj[nt][1] = dgb[j + 1];
    }

    float rsum[2][2] = {};
    float csum[8][2] = {};

    #pragma unroll
    for (int mt = 0; mt < 2; mt++) {
        #pragma unroll
        for (int rr = 0; rr < 2; rr++) {
            int i = i0 + wm * 32 + mt * 16 + grp + rr * 8;
            float di = dgb[i - i0 + i0];   // = dgb[i]
            #pragma unroll
            for (int nt = 0; nt < 8; nt++) {
                int j = j0 + wn * 64 + nt * 8 + 2 * qid;
                float dot0 = c[mt][nt][rr * 2 + 0];
                float dot1 = c[mt][nt][rr * 2 + 1];
                float d0 = (i == j)     ? 0.f : fmaxf(di + dj[nt][0] - dot0 * invM, 0.f);
                float d1 = (i == j + 1) ? 0.f : fmaxf(di + dj[nt][1] - dot1 * invM, 0.f);
                float v0 = exp2f(ALPHA * log2f(d0 + EPS));
                float v1 = exp2f(ALPHA * log2f(d1 + EPS));
                *reinterpret_cast<__half2*>(dcb + (size_t)i * DIM + j) =
                    __floats2half2_rn(v0 - 1.0f, v1 - 1.0f);
                rsum[mt][rr] += v0 + v1;
                csum[nt][0]  += v0;
                csum[nt][1]  += v1;
            }
        }
    }

    #pragma unroll
    for (int mt = 0; mt < 2; mt++)
        #pragma unroll
        for (int rr = 0; rr < 2; rr++) {
            rsum[mt][rr] += __shfl_xor_sync(0xFFFFFFFFu, rsum[mt][rr], 1);
            rsum[mt][rr] += __shfl_xor_sync(0xFFFFFFFFu, rsum[mt][rr], 2);
        }
    #pragma unroll
    for (int nt = 0; nt < 8; nt++)
        #pragma unroll
        for (int h = 0; h < 2; h++) {
            csum[nt][h] += __shfl_xor_sync(0xFFFFFFFFu, csum[nt][h], 4);
            csum[nt][h] += __shfl_xor_sync(0xFFFFFFFFu, csum[nt][h], 8);
            csum[nt][h] += __shfl_xor_sync(0xFFFFFFFFu, csum[nt][h], 16);
        }

    __syncthreads();
    float* rbuf = smem;
    float* cbuf = smem + 256;
    if (qid == 0) {
        #pragma unroll
        for (int mt = 0; mt < 2; mt++)
            #pragma unroll
            for (int rr = 0; rr < 2; rr++)
                rbuf[wn * 128 + wm * 32 + mt * 16 + rr * 8 + grp] = rsum[mt][rr];
    }
    if (grp == 0) {
        #pragma unroll
        for (int nt = 0; nt < 8; nt++) {
            cbuf[wm * 128 + wn * 64 + nt * 8 + 2 * qid + 0] = csum[nt][0];
            cbuf[wm * 128 + wn * 64 + nt * 8 + 2 * qid + 1] = csum[nt][1];
        }
    }
    __syncthreads();

    if (tid < 128) {
        float rs = rbuf[tid] + rbuf[128 + tid];
        g_part[(((size_t)b * 8 + bi) * 8 + bj) * 128 + tid] = rs;
    } else if (offdiag) {
        int t = tid - 128;
        float cs = cbuf[t] + cbuf[128 + t] + cbuf[256 + t] + cbuf[384 + t];
        g_part[(((size_t)b * 8 + bj) * 8 + bi) * 128 + t] = cs;
    }
}

// ---------------------------------------------------------------------------
// K2: row means + total mean. grid=B, block=1024.
// ---------------------------------------------------------------------------
__global__ void means_kernel() {
    int b = blockIdx.x;
    int i = threadIdx.x;
    int ti = i >> 7;
    int ii = i & 127;
    float s = 0.f;
    #pragma unroll
    for (int tj = 0; tj < 8; tj++)
        s += g_part[(((size_t)b * 8 + ti) * 8 + tj) * 128 + ii];
    float m = s * (1.f / DIM);
    g_mean[b * DIM + i] = m;

    __shared__ float sh[32];
    float t = m;
    #pragma unroll
    for (int off = 16; off > 0; off >>= 1)
        t += __shfl_down_sync(0xFFFFFFFFu, t, off);
    if ((i & 31) == 0) sh[i >> 5] = t;
    __syncthreads();
    if (i < 32) {
        float u = sh[i];
        #pragma unroll
        for (int off = 16; off > 0; off >>= 1)
            u += __shfl_down_sync(0xFFFFFFFFu, u, off);
        if (i == 0) g_tot[b] = u * (1.f / DIM);
    }
}

// ---------------------------------------------------------------------------
// K3: warp-per-row triu, half2/float2 vectorized (even-aligned pairs).
// out = v_off - mean[j] + adj, adj = tot + 1 - mean[i].
// ---------------------------------------------------------------------------
__device__ __forceinline__ long long triu_off(int i) {
    return (long long)i * (2 * DIM + 1 - i) / 2;
}

__global__ void triu_rows_kernel(float* __restrict__ out) {
    int b = blockIdx.y;
    int i = blockIdx.x * 8 + (threadIdx.x >> 5);
    int lane = threadIdx.x & 31;
    const __half* row  = g_dcov + ((size_t)b * DIM + i) * DIM;
    const float* mean = g_mean + b * DIM;
    float adj = g_tot[b] + 1.0f - mean[i];
    long long base = (long long)b * OUT_PER_B + triu_off(i) - i;

    int jbase = i & ~1;
    for (int j0 = jbase + 2 * lane; j0 < DIM; j0 += 64) {
        __half2 hv = *reinterpret_cast<const __half2*>(row + j0);
        float2 mv = *reinterpret_cast<const float2*>(mean + j0);
        float o0 = __low2float(hv) - mv.x + adj;
        float o1 = __high2float(hv) - mv.y + adj;
        if (j0 >= i) out[base + j0] = o0;      // false only for lane 0, odd i
        out[base + j0 + 1] = o1;               // j0+1 >= i and <= DIM-1 always
    }
}

// ---------------------------------------------------------------------------
extern "C" void kernel_launch(void* const* d_in, const int* in_sizes, int n_in,
                              void* d_out, int out_size) {
    const float* x = (const float*)d_in[0];
    float* out = (float*)d_out;

    static bool attr_set = false;
    if (!attr_set) {
        cudaFuncSetAttribute(syrk_dcov_mma,
                             cudaFuncAttributeMaxDynamicSharedMemorySize, SMEM_BYTES);
        attr_set = true;
    }

    tohalf_diag_kernel<<<(B * DIM) / 8, 256>>>(x);
    syrk_dcov_mma<<<dim3(NPAIRS, B), 256, SMEM_BYTES>>>(x);
    means_kernel<<<B, 1024>>>();
    triu_rows_kernel<<<dim3(DIM / 8, B), 256>>>(out);
}

// round 17
// speedup vs baseline: 1.2756x; 1.0865x over previous
#include <cuda_runtime.h>
#include <cuda_fp16.h>
#include <cstdint>

// Problem constants
constexpr int B   = 32;
constexpr int DIM = 1024;
constexpr int MM  = 512;
constexpr int OUT_PER_B = DIM * (DIM + 1) / 2;    // 524800
constexpr float ALPHA = 0.4f;
constexpr float EPS   = 1e-5f;

// Scratch
__device__ __half g_dcov[(size_t)B * DIM * DIM];  // (v - 1) as fp16, upper tiles
__device__ __half g_xh[(size_t)B * DIM * MM];     // fp16 copy of features
__device__ float  g_diag[B * DIM];
__device__ float  g_part[B * 8 * 8 * 128];
__device__ float  g_mean[B * DIM];
__device__ float  g_tot[B];

// ---------------------------------------------------------------------------
__device__ __forceinline__ void mma_f16(float* c, const uint32_t* a, const uint32_t* b) {
    asm volatile(
        "mma.sync.aligned.m16n8k16.row.col.f32.f16.f16.f32 "
        "{%0,%1,%2,%3}, {%4,%5,%6,%7}, {%8,%9}, {%0,%1,%2,%3};"
        : "+f"(c[0]), "+f"(c[1]), "+f"(c[2]), "+f"(c[3])
        : "r"(a[0]), "r"(a[1]), "r"(a[2]), "r"(a[3]), "r"(b[0]), "r"(b[1]));
}
__device__ __forceinline__ void ldsm_x4(uint32_t& r0, uint32_t& r1, uint32_t& r2,
                                        uint32_t& r3, uint32_t addr) {
    asm volatile("ldmatrix.sync.aligned.m8n8.x4.shared.b16 {%0,%1,%2,%3}, [%4];"
        : "=r"(r0), "=r"(r1), "=r"(r2), "=r"(r3) : "r"(addr));
}
__device__ __forceinline__ uint32_t smem_u32(const void* p) {
    uint32_t a;
    asm("{ .reg .u64 t; cvta.to.shared.u64 t, %1; cvt.u32.u64 %0, t; }" : "=r"(a) : "l"(p));
    return a;
}
__device__ __forceinline__ void cp16(uint32_t saddr, const void* g) {
    asm volatile("cp.async.cg.shared.global [%0], [%1], 16;" :: "r"(saddr), "l"(g));
}
#define CP_COMMIT() asm volatile("cp.async.commit_group;" ::: "memory")
#define CP_WAIT1()  asm volatile("cp.async.wait_group 1;" ::: "memory")

// MUFU transcendentals: exactly one LG2 / EX2 each.
__device__ __forceinline__ float lg2_approx(float x) {
    float r;
    asm("lg2.approx.f32 %0, %1;" : "=f"(r) : "f"(x));
    return r;
}
__device__ __forceinline__ float ex2_approx(float x) {
    float r;
    asm("ex2.approx.f32 %0, %1;" : "=f"(r) : "f"(x));
    return r;
}

// ---------------------------------------------------------------------------
// K0: fused fp32->fp16 convert + row-norm (diag). One warp per row.
// ---------------------------------------------------------------------------
__global__ void tohalf_diag_kernel(const float* __restrict__ x) {
    int row  = blockIdx.x * 8 + (threadIdx.x >> 5);
    int lane = threadIdx.x & 31;
    const float4* src = reinterpret_cast<const float4*>(x + (size_t)row * MM);
    uint2* dst = reinterpret_cast<uint2*>(g_xh + (size_t)row * MM);
    float s = 0.f;
    #pragma unroll
    for (int k = 0; k < 4; k++) {
        float4 v = src[lane + 32 * k];
        s += v.x * v.x + v.y * v.y + v.z * v.z + v.w * v.w;
        __half2 h0 = __floats2half2_rn(v.x, v.y);
        __half2 h1 = __floats2half2_rn(v.z, v.w);
        uint2 u;
        u.x = *reinterpret_cast<uint32_t*>(&h0);
        u.y = *reinterpret_cast<uint32_t*>(&h1);
        dst[lane + 32 * k] = u;
    }
    #pragma unroll
    for (int off = 16; off > 0; off >>= 1)
        s += __shfl_down_sync(0xFFFFFFFFu, s, off);
    if (lane == 0) g_diag[row] = s * (1.f / (2.f * MM));
}

// ---------------------------------------------------------------------------
// K1: FP16 mma.sync SYRK, cp.async 3-stage pipeline, ldmatrix frags,
//     below-diagonal warp skipping on diagonal tiles (row sums reconstructed
//     by symmetry), fp16-offset dcov store, deterministic partial sums.
// ---------------------------------------------------------------------------
constexpr int NTILE  = DIM / 128;
constexpr int NPAIRS = NTILE * (NTILE + 1) / 2;   // 36
constexpr int BKH    = 64;
constexpr int NITER  = MM / BKH;                  // 8
constexpr int STAGES = 3;
constexpr int ROWPH  = BKH + 8;                   // 72 halfs = 144 B row stride
constexpr int STAGE_HALFS = 128 * ROWPH;
constexpr int STAGE_BYTES = STAGE_HALFS * 2;
constexpr int SMEM_BYTES  = STAGES * 2 * STAGE_BYTES;  // 110592

constexpr int GQ_STEP   = 32 * MM;
constexpr int SQ_STEP   = 32 * ROWPH * 2;
constexpr int FRAG_STEP = 16 * ROWPH * 2;

__global__ __launch_bounds__(256, 2)
void syrk_dcov_mma(const float* __restrict__ x_unused) {
    extern __shared__ __align__(16) char smemc[];
    float* smem = reinterpret_cast<float*>(smemc);
    uint32_t sbase = smem_u32(smemc);

    int tid  = threadIdx.x;
    int wid  = tid >> 5;
    int lane = tid & 31;
    int grp  = lane >> 2;
    int qid  = lane & 3;
    int wm   = wid & 3;
    int wn   = wid >> 2;

    int p = blockIdx.x, bi = 0;
    while (p >= NTILE - bi) { p -= NTILE - bi; bi++; }
    int bj = bi + p;
    int b = blockIdx.y;

    bool diag = (bi == bj);
    bool skipwarp = diag && (wn == 0) && (wm >= 2);

    const __half* baseA = g_xh + ((size_t)b * DIM + bi * 128) * MM
                               + (size_t)(tid >> 3) * MM + (tid & 7) * 8;
    const __half* baseB = g_xh + ((size_t)b * DIM + bj * 128) * MM
                               + (size_t)(tid >> 3) * MM + (tid & 7) * 8;
    uint32_t soff0 = (uint32_t)((tid >> 3) * ROWPH * 2 + (tid & 7) * 16);

    auto issue = [&](int s) {
        uint32_t ab = sbase + (uint32_t)(s % STAGES) * (2 * STAGE_BYTES) + soff0;
        uint32_t bb = ab + STAGE_BYTES;
        const __half* ga = baseA + s * BKH;
        const __half* gb = baseB + s * BKH;
        #pragma unroll
        for (int q = 0; q < 4; q++) {
            cp16(ab + q * SQ_STEP, ga + q * GQ_STEP);
            cp16(bb + q * SQ_STEP, gb + q * GQ_STEP);
        }
    };

    uint32_t aoff0 = (uint32_t)((wm * 32 + (lane & 15)) * (ROWPH * 2) + (lane >> 4) * 16);
    uint32_t boff0 = (uint32_t)((wn * 64 + ((lane >> 4) & 1) * 8 + (lane & 7)) * (ROWPH * 2)
                                + ((lane >> 3) & 1) * 16);

    float c[2][8][4] = {};

    issue(0); CP_COMMIT();
    issue(1); CP_COMMIT();

    for (int it = 0; it < NITER; it++) {
        CP_WAIT1();
        __syncthreads();

        if (it + 2 < NITER) issue(it + 2);
        CP_COMMIT();

        if (!skipwarp) {
            uint32_t aA = sbase + (uint32_t)(it % STAGES) * (2 * STAGE_BYTES) + aoff0;
            uint32_t aB = sbase + (uint32_t)(it % STAGES) * (2 * STAGE_BYTES)
                        + STAGE_BYTES + boff0;

            #pragma unroll
            for (int ks = 0; ks < 4; ks++) {
                uint32_t kb = ks * 32;
                uint32_t af[2][4];
                #pragma unroll
                for (int mt = 0; mt < 2; mt++)
                    ldsm_x4(af[mt][0], af[mt][1], af[mt][2], af[mt][3],
                            aA + mt * FRAG_STEP + kb);
                uint32_t bf[8][2];
                #pragma unroll
                for (int pr = 0; pr < 4; pr++)
                    ldsm_x4(bf[2*pr][0], bf[2*pr][1], bf[2*pr+1][0], bf[2*pr+1][1],
                            aB + pr * FRAG_STEP + kb);
                #pragma unroll
                for (int mt = 0; mt < 2; mt++)
                    #pragma unroll
                    for (int nt = 0; nt < 8; nt++)
                        mma_f16(c[mt][nt], af[mt], bf[nt]);
            }
        }
    }

    // ---------------- Epilogue ----------------
    int i0 = bi * 128, j0 = bj * 128;
    const float invM = 1.f / (float)MM;
    __half* dcb = g_dcov + (size_t)b * DIM * DIM;
    bool offdiag = !diag;
    const float* dgb = g_diag + b * DIM;

    float rsum[2][2] = {};
    float csum[8][2] = {};

    if (!skipwarp) {
        float dj[8][2];
        #pragma unroll
        for (int nt = 0; nt < 8; nt++) {
            int j = j0 + wn * 64 + nt * 8 + 2 * qid;
            dj[nt][0] = dgb[j];
            dj[nt][1] = dgb[j + 1];
        }
        #pragma unroll
        for (int mt = 0; mt < 2; mt++) {
            #pragma unroll
            for (int rr = 0; rr < 2; rr++) {
                int i = i0 + wm * 32 + mt * 16 + grp + rr * 8;
                float di = dgb[i - i0 + i0];
                #pragma unroll
                for (int nt = 0; nt < 8; nt++) {
                    int j = j0 + wn * 64 + nt * 8 + 2 * qid;
                    float dot0 = c[mt][nt][rr * 2 + 0];
                    float dot1 = c[mt][nt][rr * 2 + 1];
                    float d0 = (i == j)     ? 0.f : fmaxf(di + dj[nt][0] - dot0 * invM, 0.f);
                    float d1 = (i == j + 1) ? 0.f : fmaxf(di + dj[nt][1] - dot1 * invM, 0.f);
                    float v0 = ex2_approx(ALPHA * lg2_approx(d0 + EPS));
                    float v1 = ex2_approx(ALPHA * lg2_approx(d1 + EPS));
                    *reinterpret_cast<__half2*>(dcb + (size_t)i * DIM + j) =
                        __floats2half2_rn(v0 - 1.0f, v1 - 1.0f);
                    rsum[mt][rr] += v0 + v1;
                    csum[nt][0]  += v0;
                    csum[nt][1]  += v1;
                }
            }
        }
    }

    #pragma unroll
    for (int mt = 0; mt < 2; mt++)
        #pragma unroll
        for (int rr = 0; rr < 2; rr++) {
            rsum[mt][rr] += __shfl_xor_sync(0xFFFFFFFFu, rsum[mt][rr], 1);
            rsum[mt][rr] += __shfl_xor_sync(0xFFFFFFFFu, rsum[mt][rr], 2);
        }
    #pragma unroll
    for (int nt = 0; nt < 8; nt++)
        #pragma unroll
        for (int h = 0; h < 2; h++) {
            csum[nt][h] += __shfl_xor_sync(0xFFFFFFFFu, csum[nt][h], 4);
            csum[nt][h] += __shfl_xor_sync(0xFFFFFFFFu, csum[nt][h], 8);
            csum[nt][h] += __shfl_xor_sync(0xFFFFFFFFu, csum[nt][h], 16);
        }

    __syncthreads();
    float* rbuf = smem;
    float* cbuf = smem + 256;
    if (qid == 0) {
        #pragma unroll
        for (int mt = 0; mt < 2; mt++)
            #pragma unroll
            for (int rr = 0; rr < 2; rr++)
                rbuf[wn * 128 + wm * 32 + mt * 16 + rr * 8 + grp] = rsum[mt][rr];
    }
    if (grp == 0) {
        #pragma unroll
        for (int nt = 0; nt < 8; nt++) {
            cbuf[wm * 128 + wn * 64 + nt * 8 + 2 * qid + 0] = csum[nt][0];
            cbuf[wm * 128 + wn * 64 + nt * 8 + 2 * qid + 1] = csum[nt][1];
        }
    }
    __syncthreads();

    if (tid < 128) {
        float rs = rbuf[tid] + rbuf[128 + tid];
        // diagonal tiles: skipped lower-left block's row sums == col sums of
        // the computed upper-right block (cbuf at cols 64..127 from wm=0,1).
        if (diag && tid >= 64) rs += cbuf[tid] + cbuf[128 + tid];
        g_part[(((size_t)b * 8 + bi) * 8 + bj) * 128 + tid] = rs;
    } else if (offdiag) {
        int t = tid - 128;
        float cs = cbuf[t] + cbuf[128 + t] + cbuf[256 + t] + cbuf[384 + t];
        g_part[(((size_t)b * 8 + bj) * 8 + bi) * 128 + t] = cs;
    }
}

// ---------------------------------------------------------------------------
// K2: row means + total mean. grid=B, block=1024.
// ---------------------------------------------------------------------------
__global__ void means_kernel() {
    int b = blockIdx.x;
    int i = threadIdx.x;
    int ti = i >> 7;
    int ii = i & 127;
    float s = 0.f;
    #pragma unroll
    for (int tj = 0; tj < 8; tj++)
        s += g_part[(((size_t)b * 8 + ti) * 8 + tj) * 128 + ii];
    float m = s * (1.f / DIM);
    g_mean[b * DIM + i] = m;

    __shared__ float sh[32];
    float t = m;
    #pragma unroll
    for (int off = 16; off > 0; off >>= 1)
        t += __shfl_down_sync(0xFFFFFFFFu, t, off);
    if ((i & 31) == 0) sh[i >> 5] = t;
    __syncthreads();
    if (i < 32) {
        float u = sh[i];
        #pragma unroll
        for (int off = 16; off > 0; off >>= 1)
            u += __shfl_down_sync(0xFFFFFFFFu, u, off);
        if (i == 0) g_tot[b] = u * (1.f / DIM);
    }
}

// ---------------------------------------------------------------------------
// K3: warp-per-row triu, half2/float2 vectorized.
// ---------------------------------------------------------------------------
__device__ __forceinline__ long long triu_off(int i) {
    return (long long)i * (2 * DIM + 1 - i) / 2;
}

__global__ void triu_rows_kernel(float* __restrict__ out) {
    int b = blockIdx.y;
    int i = blockIdx.x * 8 + (threadIdx.x >> 5);
    int lane = threadIdx.x & 31;
    const __half* row  = g_dcov + ((size_t)b * DIM + i) * DIM;
    const float* mean = g_mean + b * DIM;
    float adj = g_tot[b] + 1.0f - mean[i];
    long long base = (long long)b * OUT_PER_B + triu_off(i) - i;

    int jbase = i & ~1;
    for (int j0 = jbase + 2 * lane; j0 < DIM; j0 += 64) {
        __half2 hv = *reinterpret_cast<const __half2*>(row + j0);
        float2 mv = *reinterpret_cast<const float2*>(mean + j0);
        float o0 = __low2float(hv) - mv.x + adj;
        float o1 = __high2float(hv) - mv.y + adj;
        if (j0 >= i) out[base + j0] = o0;
        out[base + j0 + 1] = o1;
    }
}

// ---------------------------------------------------------------------------
extern "C" void kernel_launch(void* const* d_in, const int* in_sizes, int n_in,
                              void* d_out, int out_size) {
    const float* x = (const float*)d_in[0];
    float* out = (float*)d_out;

    static bool attr_set = false;
    if (!attr_set) {
        cudaFuncSetAttribute(syrk_dcov_mma,
                             cudaFuncAttributeMaxDynamicSharedMemorySize, SMEM_BYTES);
        attr_set = true;
    }

    tohalf_diag_kernel<<<(B * DIM) / 8, 256>>>(x);
    syrk_dcov_mma<<<dim3(NPAIRS, B), 256, SMEM_BYTES>>>(x);
    means_kernel<<<B, 1024>>>();
    triu_rows_kernel<<<dim3(DIM / 8, B), 256>>>(out);
}